// round 2
// baseline (speedup 1.0000x reference)
#include <cuda_runtime.h>

#define NPTS    8192
#define T       512
#define CHUNK   (NPTS / T)          // 16
#define NSTRIPS 256
#define STRIP_W 4.0f
#define STRIP_OFF 512.0f
#define R2      9.0f
#define NPAIR   6                   // B * (C-1) = 2 * 3

struct Smem {
    float          m_x[NPTS];
    float          m_y[NPTS];
    float          sum_x[NPTS];
    float          sum_y[NPTS];
    float          cnt[NPTS];
    unsigned short m_gidx[NPTS];
    unsigned short strip_list[NPTS];
    unsigned char  status[NPTS];     // phase A: mask buffer; phase C: 0=undec 1=keep 2=out
    unsigned char  m_strip[NPTS];
    int            strip_start[NSTRIPS + 1];
    int            strip_cur[NSTRIPS];
    int            tcount[T];
    int            wsum[T / 32 + 1];
    int            counters[4];
};

__global__ __launch_bounds__(T, 1)
void bbox_kernel(const float* __restrict__ seg,
                 const float* __restrict__ lidar,
                 float* __restrict__ out, int out_size)
{
    extern __shared__ char raw[];
    Smem& sm = *reinterpret_cast<Smem*>(raw);
    const int tid = threadIdx.x;
    const int bc  = blockIdx.x;        // 0..5
    const int b   = bc / 3;
    const int cls = bc % 3 + 1;        // foreground classes 1..3

    const float* s0 = seg + (size_t)b * 4 * NPTS;
    const float* lx = lidar + (size_t)b * 2 * NPTS;
    const float* ly = lx + NPTS;

    // ---------------- Phase A1: per-point class argmax -> mask (coalesced) ----------------
    for (int g = tid; g < NPTS; g += T) {
        float v0 = s0[g];
        float v1 = s0[NPTS + g];
        float v2 = s0[2 * NPTS + g];
        float v3 = s0[3 * NPTS + g];
        int a = 0; float bv = v0;
        if (v1 > bv) { bv = v1; a = 1; }   // strict > : first-max tie-break like jnp.argmax
        if (v2 > bv) { bv = v2; a = 2; }
        if (v3 > bv) { bv = v3; a = 3; }
        sm.status[g] = (a == cls) ? (unsigned char)1 : (unsigned char)0;
    }
    __syncthreads();

    // ---------------- Phase A2: order-preserving compaction of masked points ----------------
    {
        const int base = tid * CHUNK;
        int cl = 0;
        for (int k = 0; k < CHUNK; k++) cl += sm.status[base + k];
        sm.tcount[tid] = cl;
        __syncthreads();

        const int lane = tid & 31, w = tid >> 5;
        int v = sm.tcount[tid];
        for (int d = 1; d < 32; d <<= 1) {
            int n = __shfl_up_sync(0xffffffffu, v, d);
            if (lane >= d) v += n;
        }
        if (lane == 31) sm.wsum[w] = v;
        __syncthreads();
        if (w == 0) {
            int nv = (lane < T / 32) ? sm.wsum[lane] : 0;
            for (int d = 1; d < 32; d <<= 1) {
                int n = __shfl_up_sync(0xffffffffu, nv, d);
                if (lane >= d) nv += n;
            }
            if (lane < T / 32) sm.wsum[lane] = nv;        // inclusive across warps
            if (lane == T / 32 - 1) sm.counters[0] = nv;  // M = total masked
        }
        __syncthreads();

        const int wexcl = (w == 0) ? 0 : sm.wsum[w - 1];
        int pos = wexcl + (v - cl);                       // exclusive prefix for this thread
        for (int k = 0; k < CHUNK; k++) {
            const int g = base + k;
            if (sm.status[g]) {
                const float px = lx[g], py = ly[g];
                sm.m_x[pos] = px;
                sm.m_y[pos] = py;
                sm.m_gidx[pos] = (unsigned short)g;
                int st = (int)floorf(__fmul_rn(__fadd_rn(px, STRIP_OFF), 1.0f / STRIP_W));
                st = min(max(st, 0), NSTRIPS - 1);        // monotone clamp: window stays valid
                sm.m_strip[pos] = (unsigned char)st;
                pos++;
            }
        }
    }
    __syncthreads();
    const int M = sm.counters[0];

    // ---------------- Phase B: strip CSR (histogram, scan, scatter) ----------------
    for (int s = tid; s <= NSTRIPS; s += T) sm.strip_start[s] = 0;
    __syncthreads();
    for (int m = tid; m < M; m += T)
        atomicAdd(&sm.strip_start[(int)sm.m_strip[m] + 1], 1);
    __syncthreads();
    if (tid < 32) {
        const int lane = tid;
        int c[8]; int s = 0;
        for (int k = 0; k < 8; k++) { c[k] = sm.strip_start[lane * 8 + k + 1]; s += c[k]; }
        int incl = s;
        for (int d = 1; d < 32; d <<= 1) {
            int n = __shfl_up_sync(0xffffffffu, incl, d);
            if (lane >= d) incl += n;
        }
        int acc = incl - s;
        for (int k = 0; k < 8; k++) { acc += c[k]; sm.strip_start[lane * 8 + k + 1] = acc; }
        if (lane == 0) sm.strip_start[0] = 0;
    }
    __syncthreads();
    for (int s = tid; s < NSTRIPS; s += T) sm.strip_cur[s] = sm.strip_start[s];
    __syncthreads();
    for (int m = tid; m < M; m += T) {
        const int pos = atomicAdd(&sm.strip_cur[(int)sm.m_strip[m]], 1);
        sm.strip_list[pos] = (unsigned short)m;
    }
    // re-init status for NMS (safe: different array than strip_list scatter)
    for (int m = tid; m < M; m += T) sm.status[m] = 0;
    __syncthreads();

    // ---------------- Phase C: greedy radius-NMS by monotone parallel relaxation ----------------
    // Unique fixpoint of the greedy scan => racy-but-monotone updates give the exact result.
    for (;;) {
        if (tid == 0) sm.counters[1] = 0;
        __syncthreads();
        for (int m = tid; m < M; m += T) {
            if (sm.status[m] != 0) continue;
            const float px = sm.m_x[m], py = sm.m_y[m];
            const int s = sm.m_strip[m];
            const int sa = max(s - 1, 0), sb = min(s + 1, NSTRIPS - 1);
            bool any_undec = false, outp = false;
            for (int ss = sa; ss <= sb && !outp; ss++) {
                const int p1 = sm.strip_start[ss + 1];
                for (int p = sm.strip_start[ss]; p < p1; p++) {
                    const int j = sm.strip_list[p];
                    if (j >= m) continue;                 // earlier-in-order only
                    const float dx = __fadd_rn(sm.m_x[j], -px);
                    const float dy = __fadd_rn(sm.m_y[j], -py);
                    const float d2 = __fadd_rn(__fmul_rn(dx, dx), __fmul_rn(dy, dy));
                    if (d2 < R2) {
                        const unsigned char st = sm.status[j];
                        if (st == 1) { outp = true; break; }
                        if (st == 0) any_undec = true;
                    }
                }
            }
            if (outp)             sm.status[m] = 2;
            else if (!any_undec)  sm.status[m] = 1;
            else                  atomicAdd(&sm.counters[1], 1);
        }
        __syncthreads();
        const int rem = sm.counters[1];
        __syncthreads();
        if (rem == 0) break;
    }

    // ---------------- Phase E: k-means assignment (1 iter) + segment sums ----------------
    for (int m = tid; m < M; m += T) { sm.sum_x[m] = 0.f; sm.sum_y[m] = 0.f; sm.cnt[m] = 0.f; }
    __syncthreads();
    for (int m = tid; m < M; m += T) {
        int tgt;
        if (sm.status[m] == 1) {
            tgt = m;   // self is the unique 0-distance kept center
        } else {
            const float px = sm.m_x[m], py = sm.m_y[m];
            const int s = sm.m_strip[m];
            float best = 3.4e38f; int bj = -1;
            const int sa = max(s - 1, 0), sb = min(s + 1, NSTRIPS - 1);
            for (int ss = sa; ss <= sb; ss++) {
                const int p1 = sm.strip_start[ss + 1];
                for (int p = sm.strip_start[ss]; p < p1; p++) {
                    const int j = sm.strip_list[p];
                    if (sm.status[j] != 1) continue;
                    const float dx = __fadd_rn(px, -sm.m_x[j]);
                    const float dy = __fadd_rn(py, -sm.m_y[j]);
                    const float d2 = __fadd_rn(__fmul_rn(dx, dx), __fmul_rn(dy, dy));
                    if (d2 < best || (d2 == best && j < bj)) { best = d2; bj = j; }
                }
            }
            tgt = bj;   // provably >= 0: suppressor lies within distance < 3
        }
        if (tgt >= 0) {
            atomicAdd(&sm.sum_x[tgt], sm.m_x[m]);
            atomicAdd(&sm.sum_y[tgt], sm.m_y[m]);
            atomicAdd(&sm.cnt[tgt], 1.0f);
        }
    }
    __syncthreads();

    // ---------------- Phase F: write centers (+ keep) ----------------
    float* ctr = out + (size_t)bc * NPTS * 2;
    for (int g = tid; g < NPTS; g += T) { ctr[2 * g] = 0.f; ctr[2 * g + 1] = 0.f; }
    const bool has_keep = (out_size >= NPAIR * NPTS * 2 + NPAIR * NPTS);
    float* kp = out + (size_t)NPAIR * NPTS * 2 + (size_t)bc * NPTS;
    if (has_keep)
        for (int g = tid; g < NPTS; g += T) kp[g] = 0.f;
    __syncthreads();
    for (int m = tid; m < M; m += T) {
        if (sm.status[m] == 1) {
            const int g = sm.m_gidx[m];
            const float cn = sm.cnt[m];            // >= 1 always (self-assigned)
            ctr[2 * g]     = __fdiv_rn(sm.sum_x[m], cn);
            ctr[2 * g + 1] = __fdiv_rn(sm.sum_y[m], cn);
            if (has_keep) kp[g] = 1.0f;
        }
    }
}

extern "C" void kernel_launch(void* const* d_in, const int* in_sizes, int n_in,
                              void* d_out, int out_size)
{
    const float* seg   = (const float*)d_in[0];
    const float* lidar = (const float*)d_in[1];
    (void)in_sizes; (void)n_in;

    cudaFuncSetAttribute(bbox_kernel,
                         cudaFuncAttributeMaxDynamicSharedMemorySize,
                         (int)sizeof(Smem));
    bbox_kernel<<<NPAIR, T, sizeof(Smem)>>>(seg, lidar, (float*)d_out, out_size);
}

// round 3
// speedup vs baseline: 3.6337x; 3.6337x over previous
#include <cuda_runtime.h>

#define NPTS    8192
#define T       1024
#define CHUNK   (NPTS / T)          // 8
#define NW      (T / 32)            // 32 warps
#define NSTRIPS 256
#define STRIP_W 4.0f
#define STRIP_OFF 512.0f
#define R2      9.0f
#define NPAIR   6                   // B * (C-1)
#define KNBR    6                   // adjacency cap; overflow -> geometric fallback

struct Smem {
    union {                                   // 98304 B, time-multiplexed
        struct {                              // phase A2/B temps (original compact order)
            float          cr_x[NPTS];
            float          cr_y[NPTS];
            unsigned short cr_gidx[NPTS];
            unsigned char  cr_strip[NPTS];
        } a;                                  // 90112 B
        unsigned short nbr[NPTS * KNBR];      // phase C adjacency: 98304 B
        struct {                              // phase E k-means sums: 98304 B
            float sum_x[NPTS];
            float sum_y[NPTS];
            float cnt[NPTS];
        } e;
    } u;
    float2         s_xy[NPTS];                // sorted-by-strip coords (65536 B)
    unsigned short s_rank[NPTS];              // original compact index (order semantics)
    unsigned short s_gidx[NPTS];              // original grid index
    unsigned char  status[NPTS];              // A1 mask (by g) -> NMS status (by sorted p)
    unsigned char  nbr_cnt[NPTS];             // low 7 bits count, bit7 = overflow
    int            strip_start[NSTRIPS + 1];
    int            strip_cur[NSTRIPS];
    int            tcount[T];
    int            wsum[NW];
    int            counters[4];
};

__device__ __forceinline__ int strip_of(float x) {
    int st = (int)floorf(__fmul_rn(__fadd_rn(x, STRIP_OFF), 1.0f / STRIP_W));
    return min(max(st, 0), NSTRIPS - 1);
}

__global__ __launch_bounds__(T, 1)
void bbox_kernel(const float* __restrict__ seg,
                 const float* __restrict__ lidar,
                 float* __restrict__ out, int out_size)
{
    extern __shared__ char raw[];
    Smem& sm = *reinterpret_cast<Smem*>(raw);
    const int tid = threadIdx.x;
    const int bc  = blockIdx.x;
    const int b   = bc / 3;
    const int cls = bc % 3 + 1;

    const float* s0 = seg + (size_t)b * 4 * NPTS;
    const float* lx = lidar + (size_t)b * 2 * NPTS;
    const float* ly = lx + NPTS;

    // ---------------- A1: class argmax -> mask (by grid idx) ----------------
    for (int g = tid; g < NPTS; g += T) {
        float v0 = s0[g];
        float v1 = s0[NPTS + g];
        float v2 = s0[2 * NPTS + g];
        float v3 = s0[3 * NPTS + g];
        int a = 0; float bv = v0;
        if (v1 > bv) { bv = v1; a = 1; }   // strict >: first-max tie-break (jnp.argmax)
        if (v2 > bv) { bv = v2; a = 2; }
        if (v3 > bv) { bv = v3; a = 3; }
        sm.status[g] = (a == cls) ? (unsigned char)1 : (unsigned char)0;
    }
    __syncthreads();

    // ---------------- A2: order-preserving compaction ----------------
    {
        const int base = tid * CHUNK;
        int cl = 0;
        for (int k = 0; k < CHUNK; k++) cl += sm.status[base + k];
        sm.tcount[tid] = cl;
        __syncthreads();

        const int lane = tid & 31, w = tid >> 5;
        int v = sm.tcount[tid];
        for (int d = 1; d < 32; d <<= 1) {
            int n = __shfl_up_sync(0xffffffffu, v, d);
            if (lane >= d) v += n;
        }
        if (lane == 31) sm.wsum[w] = v;
        __syncthreads();
        if (w == 0) {
            int nv = sm.wsum[lane];                      // NW == 32
            for (int d = 1; d < 32; d <<= 1) {
                int n = __shfl_up_sync(0xffffffffu, nv, d);
                if (lane >= d) nv += n;
            }
            sm.wsum[lane] = nv;                          // inclusive across warps
            if (lane == NW - 1) sm.counters[0] = nv;     // M
        }
        __syncthreads();

        const int wexcl = (w == 0) ? 0 : sm.wsum[w - 1];
        int pos = wexcl + (v - cl);
        for (int k = 0; k < CHUNK; k++) {
            const int g = base + k;
            if (sm.status[g]) {
                const float px = lx[g], py = ly[g];
                sm.u.a.cr_x[pos] = px;
                sm.u.a.cr_y[pos] = py;
                sm.u.a.cr_gidx[pos] = (unsigned short)g;
                sm.u.a.cr_strip[pos] = (unsigned char)strip_of(px);
                pos++;
            }
        }
    }
    __syncthreads();
    const int M = sm.counters[0];

    // ---------------- B: strip histogram + scan + scatter (sorted layout) ----------------
    for (int s = tid; s <= NSTRIPS; s += T) sm.strip_start[s] = 0;
    __syncthreads();
    for (int m = tid; m < M; m += T)
        atomicAdd(&sm.strip_start[(int)sm.u.a.cr_strip[m] + 1], 1);
    __syncthreads();
    if (tid < 32) {
        const int lane = tid;
        int c[8]; int s = 0;
        for (int k = 0; k < 8; k++) { c[k] = sm.strip_start[lane * 8 + k + 1]; s += c[k]; }
        int incl = s;
        for (int d = 1; d < 32; d <<= 1) {
            int n = __shfl_up_sync(0xffffffffu, incl, d);
            if (lane >= d) incl += n;
        }
        int acc = incl - s;
        for (int k = 0; k < 8; k++) { acc += c[k]; sm.strip_start[lane * 8 + k + 1] = acc; }
        if (lane == 0) sm.strip_start[0] = 0;
    }
    __syncthreads();
    for (int s = tid; s < NSTRIPS; s += T) sm.strip_cur[s] = sm.strip_start[s];
    __syncthreads();
    for (int m = tid; m < M; m += T) {
        const int pos = atomicAdd(&sm.strip_cur[(int)sm.u.a.cr_strip[m]], 1);
        sm.s_xy[pos]   = make_float2(sm.u.a.cr_x[m], sm.u.a.cr_y[m]);
        sm.s_rank[pos] = (unsigned short)m;
        sm.s_gidx[pos] = sm.u.a.cr_gidx[m];
    }
    for (int p = tid; p < M; p += T) sm.status[p] = 0;   // reset for NMS
    __syncthreads();   // cr_* fully consumed; union region now free for nbr

    // ---------------- C1: one-shot adjacency build (earlier in-radius neighbors) --------
    for (int p = tid; p < M; p += T) {
        const float2 me = sm.s_xy[p];
        const int myrank = sm.s_rank[p];
        const int s  = strip_of(me.x);
        const int q0 = sm.strip_start[max(s - 1, 0)];
        const int q1 = sm.strip_start[min(s + 1, NSTRIPS - 1) + 1];
        int c = 0; bool ovf = false;
        for (int q = q0; q < q1; q++) {
            if ((int)sm.s_rank[q] >= myrank) continue;
            const float2 o = sm.s_xy[q];
            const float dx = __fadd_rn(o.x, -me.x);
            const float dy = __fadd_rn(o.y, -me.y);
            const float d2 = __fadd_rn(__fmul_rn(dx, dx), __fmul_rn(dy, dy));
            if (d2 < R2) {
                if (c < KNBR) sm.nbr_cnt[p] = 0, sm.u.nbr[p * KNBR + c] = (unsigned short)q;
                c++;
                if (c > KNBR) { ovf = true; break; }
            }
        }
        sm.nbr_cnt[p] = ovf ? (unsigned char)0x80 : (unsigned char)min(c, KNBR);
    }
    __syncthreads();

    // ---------------- C2: monotone relaxation to the greedy-NMS fixpoint ----------------
    for (;;) {
        if (tid == 0) sm.counters[1] = 0;
        __syncthreads();
        for (int p = tid; p < M; p += T) {
            if (sm.status[p] != 0) continue;
            bool any_undec = false, outp = false;
            const unsigned char nc = sm.nbr_cnt[p];
            if (!(nc & 0x80)) {
                for (int k = 0; k < (int)nc; k++) {
                    const unsigned char st = sm.status[sm.u.nbr[p * KNBR + k]];
                    if (st == 1) { outp = true; break; }
                    if (st == 0) any_undec = true;
                }
            } else {  // rare fallback: geometric scan
                const float2 me = sm.s_xy[p];
                const int myrank = sm.s_rank[p];
                const int s  = strip_of(me.x);
                const int q0 = sm.strip_start[max(s - 1, 0)];
                const int q1 = sm.strip_start[min(s + 1, NSTRIPS - 1) + 1];
                for (int q = q0; q < q1 && !outp; q++) {
                    if ((int)sm.s_rank[q] >= myrank) continue;
                    const float2 o = sm.s_xy[q];
                    const float dx = __fadd_rn(o.x, -me.x);
                    const float dy = __fadd_rn(o.y, -me.y);
                    const float d2 = __fadd_rn(__fmul_rn(dx, dx), __fmul_rn(dy, dy));
                    if (d2 < R2) {
                        const unsigned char st = sm.status[q];
                        if (st == 1) outp = true;
                        else if (st == 0) any_undec = true;
                    }
                }
            }
            if (outp)            sm.status[p] = 2;
            else if (!any_undec) sm.status[p] = 1;
            else                 atomicAdd(&sm.counters[1], 1);
        }
        __syncthreads();
        const int rem = sm.counters[1];
        __syncthreads();
        if (rem == 0) break;
    }
    // union region (nbr) no longer needed -> k-means sums

    // ---------------- E: k-means assign (1 iter) + segment sums ----------------
    for (int p = tid; p < M; p += T) { sm.u.e.sum_x[p] = 0.f; sm.u.e.sum_y[p] = 0.f; sm.u.e.cnt[p] = 0.f; }
    __syncthreads();
    for (int p = tid; p < M; p += T) {
        int tgt;
        if (sm.status[p] == 1) {
            tgt = p;                                   // unique 0-distance kept center
        } else {
            const float2 me = sm.s_xy[p];
            const int s  = strip_of(me.x);
            const int q0 = sm.strip_start[max(s - 1, 0)];
            const int q1 = sm.strip_start[min(s + 1, NSTRIPS - 1) + 1];
            float best = 3.4e38f; int bj = -1, brank = 1 << 30;
            for (int q = q0; q < q1; q++) {
                if (sm.status[q] != 1) continue;
                const float2 o = sm.s_xy[q];
                const float dx = __fadd_rn(me.x, -o.x);
                const float dy = __fadd_rn(me.y, -o.y);
                const float d2 = __fadd_rn(__fmul_rn(dx, dx), __fmul_rn(dy, dy));
                const int rq = sm.s_rank[q];
                if (d2 < best || (d2 == best && rq < brank)) { best = d2; bj = q; brank = rq; }
            }
            tgt = bj;                                  // >=0: suppressor within distance < 3
        }
        if (tgt >= 0) {
            const float2 me = sm.s_xy[p];
            atomicAdd(&sm.u.e.sum_x[tgt], me.x);
            atomicAdd(&sm.u.e.sum_y[tgt], me.y);
            atomicAdd(&sm.u.e.cnt[tgt], 1.0f);
        }
    }
    __syncthreads();

    // ---------------- F: write centers (+ keep) ----------------
    float* ctr = out + (size_t)bc * NPTS * 2;
    for (int g = tid; g < NPTS; g += T) { ctr[2 * g] = 0.f; ctr[2 * g + 1] = 0.f; }
    const bool has_keep = (out_size >= NPAIR * NPTS * 2 + NPAIR * NPTS);
    float* kp = out + (size_t)NPAIR * NPTS * 2 + (size_t)bc * NPTS;
    if (has_keep)
        for (int g = tid; g < NPTS; g += T) kp[g] = 0.f;
    __syncthreads();
    for (int p = tid; p < M; p += T) {
        if (sm.status[p] == 1) {
            const int g = sm.s_gidx[p];
            const float cn = sm.u.e.cnt[p];           // >= 1 (self-assigned)
            ctr[2 * g]     = __fdiv_rn(sm.u.e.sum_x[p], cn);
            ctr[2 * g + 1] = __fdiv_rn(sm.u.e.sum_y[p], cn);
            if (has_keep) kp[g] = 1.0f;
        }
    }
}

extern "C" void kernel_launch(void* const* d_in, const int* in_sizes, int n_in,
                              void* d_out, int out_size)
{
    const float* seg   = (const float*)d_in[0];
    const float* lidar = (const float*)d_in[1];
    (void)in_sizes; (void)n_in;

    cudaFuncSetAttribute(bbox_kernel,
                         cudaFuncAttributeMaxDynamicSharedMemorySize,
                         (int)sizeof(Smem));
    bbox_kernel<<<NPAIR, T, sizeof(Smem)>>>(seg, lidar, (float*)d_out, out_size);
}

// round 5
// speedup vs baseline: 6.3359x; 1.7436x over previous
#include <cuda_runtime.h>

#define NPTS    8192
#define T       1024
#define CHUNK   8                   // NPTS / T
#define NW      32                  // warps
#define NCX     128                 // x cells, width 4
#define NCY     64                  // y cells, width 8
#define NCELLS  (NCX * NCY)         // 8192
#define EXT     256.0f
#define R2      9.0f
#define NPAIR   6
#define KNBR    6

struct Smem {
    union {                                  // 98304 B, time-multiplexed
        int            hist[NCELLS];         // histogram -> scatter cursors (32 KB)
        unsigned short nbr[NPTS * KNBR];     // NMS adjacency (96 KB)
        struct { float sum_x[NPTS], sum_y[NPTS], cnt[NPTS]; } e;  // k-means (96 KB)
    } u;
    float2         s_xy[NPTS];               // cell-sorted coords
    unsigned short s_rank[NPTS];             // original compact index (greedy order)
    unsigned short s_gidx[NPTS];             // original grid index
    unsigned char  status[NPTS];             // mask (by g) -> NMS status (by sorted p)
    unsigned char  nbr_cnt[NPTS];            // low bits count, bit7 = overflow
    unsigned short cstart[NCELLS + 1];       // cell CSR starts (persists through C/E)
    int            wsum[NW];
    int            counters[4];
};

__device__ __forceinline__ int cellx(float x) {
    return min(max((int)floorf((x + EXT) * 0.25f), 0), NCX - 1);
}
__device__ __forceinline__ int celly(float y) {
    return min(max((int)floorf((y + EXT) * 0.125f), 0), NCY - 1);
}

__global__ __launch_bounds__(T, 1)
void bbox_kernel(const float* __restrict__ seg,
                 const float* __restrict__ lidar,
                 float* __restrict__ out, int out_size)
{
    extern __shared__ char raw[];
    Smem& sm = *reinterpret_cast<Smem*>(raw);
    const int tid  = threadIdx.x;
    const int lane = tid & 31, w = tid >> 5;
    const int bc   = blockIdx.x;
    const int b    = bc / 3;
    const int cls  = bc % 3 + 1;

    const float* s0 = seg + (size_t)b * 4 * NPTS;
    const float* lx = lidar + (size_t)b * 2 * NPTS;
    const float* ly = lx + NPTS;

    // ---------------- A1: argmax mask + cell histogram ----------------
    for (int i = tid; i < NCELLS; i += T) sm.u.hist[i] = 0;
    __syncthreads();
    for (int g = tid; g < NPTS; g += T) {
        float v0 = s0[g];
        float v1 = s0[NPTS + g];
        float v2 = s0[2 * NPTS + g];
        float v3 = s0[3 * NPTS + g];
        int a = 0; float bv = v0;
        if (v1 > bv) { bv = v1; a = 1; }    // strict >: jnp.argmax first-max tie-break
        if (v2 > bv) { bv = v2; a = 2; }
        if (v3 > bv) { bv = v3; a = 3; }
        const bool msk = (a == cls);
        sm.status[g] = msk ? (unsigned char)1 : (unsigned char)0;
        if (msk) {
            const int cell = celly(ly[g]) * NCX + cellx(lx[g]);
            atomicAdd(&sm.u.hist[cell], 1);
        }
    }
    __syncthreads();

    // ---------------- A2: exclusive scan of cell histogram -> cstart + cursors ----------
    {
        const int base = tid * 8;            // 1024 threads x 8 cells
        int c[8]; int ssum = 0;
        for (int k = 0; k < 8; k++) { c[k] = sm.u.hist[base + k]; ssum += c[k]; }
        int incl = ssum;
        for (int d = 1; d < 32; d <<= 1) {
            int n = __shfl_up_sync(0xffffffffu, incl, d);
            if (lane >= d) incl += n;
        }
        if (lane == 31) sm.wsum[w] = incl;
        __syncthreads();
        if (w == 0) {
            int nv = sm.wsum[lane];
            for (int d = 1; d < 32; d <<= 1) {
                int n = __shfl_up_sync(0xffffffffu, nv, d);
                if (lane >= d) nv += n;
            }
            sm.wsum[lane] = nv;
        }
        __syncthreads();
        int acc = ((w == 0) ? 0 : sm.wsum[w - 1]) + incl - ssum;
        for (int k = 0; k < 8; k++) {
            sm.u.hist[base + k]   = acc;                    // scatter cursor
            sm.cstart[base + k]   = (unsigned short)acc;    // CSR start
            acc += c[k];
        }
        if (tid == T - 1) sm.cstart[NCELLS] = (unsigned short)acc;
    }
    __syncthreads();

    // ---------------- A3: rank scan + direct scatter to cell-sorted layout -------------
    {
        const int base = tid * CHUNK;
        int cl = 0;
        for (int k = 0; k < CHUNK; k++) cl += sm.status[base + k];
        int v = cl;
        for (int d = 1; d < 32; d <<= 1) {
            int n = __shfl_up_sync(0xffffffffu, v, d);
            if (lane >= d) v += n;
        }
        if (lane == 31) sm.wsum[w] = v;
        __syncthreads();
        if (w == 0) {
            int nv = sm.wsum[lane];
            for (int d = 1; d < 32; d <<= 1) {
                int n = __shfl_up_sync(0xffffffffu, nv, d);
                if (lane >= d) nv += n;
            }
            sm.wsum[lane] = nv;
            if (lane == NW - 1) sm.counters[0] = nv;        // M
        }
        __syncthreads();
        int rank = ((w == 0) ? 0 : sm.wsum[w - 1]) + v - cl;
        for (int k = 0; k < CHUNK; k++) {
            const int g = base + k;
            if (sm.status[g]) {
                const float px = lx[g], py = ly[g];
                const int cell = celly(py) * NCX + cellx(px);
                const int pos = atomicAdd(&sm.u.hist[cell], 1);
                sm.s_xy[pos]   = make_float2(px, py);
                sm.s_rank[pos] = (unsigned short)rank;
                sm.s_gidx[pos] = (unsigned short)g;
                rank++;
            }
        }
    }
    __syncthreads();
    const int M = sm.counters[0];
    for (int p = tid; p < M; p += T) sm.status[p] = 0;      // reset for NMS
    __syncthreads();                                        // cursors dead -> union free

    // ---------------- C1: one-shot adjacency (earlier in-radius neighbors) --------------
    for (int p = tid; p < M; p += T) {
        const float2 me = sm.s_xy[p];
        const int myr = sm.s_rank[p];
        const int cx = cellx(me.x), cy = celly(me.y);
        const int cxa = max(cx - 1, 0), cxb = min(cx + 1, NCX - 1);
        const int rya = max(cy - 1, 0), ryb = min(cy + 1, NCY - 1);
        int c = 0; bool ovf = false;
        for (int ry = rya; ry <= ryb && !ovf; ry++) {
            const int q0 = sm.cstart[ry * NCX + cxa];
            const int q1 = sm.cstart[ry * NCX + cxb + 1];
            for (int q = q0; q < q1; q++) {
                if ((int)sm.s_rank[q] >= myr) continue;
                const float2 o = sm.s_xy[q];
                const float dx = __fadd_rn(o.x, -me.x);
                const float dy = __fadd_rn(o.y, -me.y);
                const float d2 = __fadd_rn(__fmul_rn(dx, dx), __fmul_rn(dy, dy));
                if (d2 < R2) {
                    if (c < KNBR) sm.u.nbr[p * KNBR + c] = (unsigned short)q;
                    c++;
                    if (c > KNBR) { ovf = true; break; }
                }
            }
        }
        sm.nbr_cnt[p] = ovf ? (unsigned char)0x80 : (unsigned char)c;
    }
    __syncthreads();

    // ---------------- C2: monotone relaxation to greedy-NMS fixpoint --------------------
    for (;;) {
        if (tid == 0) sm.counters[1] = 0;
        __syncthreads();
        int pend = 0;
        for (int p = tid; p < M; p += T) {
            if (sm.status[p] != 0) continue;
            bool any_undec = false, outp = false;
            const unsigned char nc = sm.nbr_cnt[p];
            if (!(nc & 0x80)) {
                for (int k = 0; k < (int)nc; k++) {
                    const unsigned char st = sm.status[sm.u.nbr[p * KNBR + k]];
                    if (st == 1) { outp = true; break; }
                    if (st == 0) any_undec = true;
                }
            } else {                                       // rare geometric fallback
                const float2 me = sm.s_xy[p];
                const int myr = sm.s_rank[p];
                const int cx = cellx(me.x), cy = celly(me.y);
                const int cxa = max(cx - 1, 0), cxb = min(cx + 1, NCX - 1);
                const int rya = max(cy - 1, 0), ryb = min(cy + 1, NCY - 1);
                for (int ry = rya; ry <= ryb && !outp; ry++) {
                    const int q0 = sm.cstart[ry * NCX + cxa];
                    const int q1 = sm.cstart[ry * NCX + cxb + 1];
                    for (int q = q0; q < q1; q++) {
                        if ((int)sm.s_rank[q] >= myr) continue;
                        const float2 o = sm.s_xy[q];
                        const float dx = __fadd_rn(o.x, -me.x);
                        const float dy = __fadd_rn(o.y, -me.y);
                        const float d2 = __fadd_rn(__fmul_rn(dx, dx), __fmul_rn(dy, dy));
                        if (d2 < R2) {
                            const unsigned char st = sm.status[q];
                            if (st == 1) { outp = true; break; }
                            if (st == 0) any_undec = true;
                        }
                    }
                }
            }
            if (outp)            sm.status[p] = 2;
            else if (!any_undec) sm.status[p] = 1;
            else                 pend++;
        }
        for (int d = 16; d > 0; d >>= 1) pend += __shfl_down_sync(0xffffffffu, pend, d);
        if (lane == 0 && pend) atomicAdd(&sm.counters[1], pend);
        __syncthreads();
        const int rem = sm.counters[1];
        __syncthreads();
        if (rem == 0) break;
    }
    // union (nbr) dead -> k-means sums

    // ---------------- E: k-means assign (1 iter) + segment sums -------------------------
    for (int p = tid; p < M; p += T) { sm.u.e.sum_x[p] = 0.f; sm.u.e.sum_y[p] = 0.f; sm.u.e.cnt[p] = 0.f; }
    __syncthreads();
    for (int p = tid; p < M; p += T) {
        int tgt;
        if (sm.status[p] == 1) {
            tgt = p;                                       // unique 0-distance kept center
        } else {
            const float2 me = sm.s_xy[p];
            const int cx = cellx(me.x), cy = celly(me.y);
            const int cxa = max(cx - 1, 0), cxb = min(cx + 1, NCX - 1);
            const int rya = max(cy - 1, 0), ryb = min(cy + 1, NCY - 1);
            float best = 3.4e38f; int bj = -1, brank = 1 << 30;
            for (int ry = rya; ry <= ryb; ry++) {
                const int q0 = sm.cstart[ry * NCX + cxa];
                const int q1 = sm.cstart[ry * NCX + cxb + 1];
                for (int q = q0; q < q1; q++) {
                    if (sm.status[q] != 1) continue;
                    const float2 o = sm.s_xy[q];
                    const float dx = __fadd_rn(me.x, -o.x);
                    const float dy = __fadd_rn(me.y, -o.y);
                    const float d2 = __fadd_rn(__fmul_rn(dx, dx), __fmul_rn(dy, dy));
                    const int rq = sm.s_rank[q];
                    if (d2 < best || (d2 == best && rq < brank)) { best = d2; bj = q; brank = rq; }
                }
            }
            tgt = bj;                                      // >=0: suppressor within dist < 3
        }
        if (tgt >= 0) {
            const float2 me = sm.s_xy[p];
            atomicAdd(&sm.u.e.sum_x[tgt], me.x);
            atomicAdd(&sm.u.e.sum_y[tgt], me.y);
            atomicAdd(&sm.u.e.cnt[tgt], 1.0f);
        }
    }
    __syncthreads();

    // ---------------- F: write centers (+ keep) ----------------------------------------
    float* ctr = out + (size_t)bc * NPTS * 2;
    for (int g = tid; g < NPTS; g += T) { ctr[2 * g] = 0.f; ctr[2 * g + 1] = 0.f; }
    const bool has_keep = (out_size >= NPAIR * NPTS * 2 + NPAIR * NPTS);
    float* kp = out + (size_t)NPAIR * NPTS * 2 + (size_t)bc * NPTS;
    if (has_keep)
        for (int g = tid; g < NPTS; g += T) kp[g] = 0.f;
    __syncthreads();
    for (int p = tid; p < M; p += T) {
        if (sm.status[p] == 1) {
            const int g = sm.s_gidx[p];
            const float cn = sm.u.e.cnt[p];               // >= 1 (self-assigned)
            ctr[2 * g]     = __fdiv_rn(sm.u.e.sum_x[p], cn);
            ctr[2 * g + 1] = __fdiv_rn(sm.u.e.sum_y[p], cn);
            if (has_keep) kp[g] = 1.0f;
        }
    }
}

extern "C" void kernel_launch(void* const* d_in, const int* in_sizes, int n_in,
                              void* d_out, int out_size)
{
    const float* seg   = (const float*)d_in[0];
    const float* lidar = (const float*)d_in[1];
    (void)in_sizes; (void)n_in;

    cudaFuncSetAttribute(bbox_kernel,
                         cudaFuncAttributeMaxDynamicSharedMemorySize,
                         (int)sizeof(Smem));
    bbox_kernel<<<NPAIR, T, sizeof(Smem)>>>(seg, lidar, (float*)d_out, out_size);
}